// round 14
// baseline (speedup 1.0000x reference)
#include <cuda_runtime.h>
#include <cuda_fp16.h>
#include <math.h>
#include <stdint.h>

#define DD 1024
#define EE 8
#define NTOK 8192
#define NROW 16384
#define RPAD 17408
#define NKEY 64
#define NBLK 128
// GEMM smem layout (dynamic):
//  [0]          A stage0 (128 x 72 halves)   18432 B
//  [18432]      A stage1                     18432 B
//  [36864]      B16 stage0 (64 x 136 halves) 17408 B
//  [54272]      B16 stage1                   17408 B
//  [71680]      B32 staging (64 x 132 float) 33792 B
#define A_ST    18432
#define B16_OFF 36864
#define B16_ST  17408
#define B32_OFF 71680
#define GEMM_SMEM 105472

// ------------------------ scratch (device globals) ------------------------
static __device__ __align__(256) __half g_ah[(size_t)RPAD*DD];    // fp16 xg
static __device__ __align__(256) __half g_hh[(size_t)RPAD*DD];    // fp16 gelu(h)
static __device__ __align__(256) float  g_y[(size_t)RPAD*DD];     // fp32 y (gemm2 out)
static __device__ __align__(256) float2 g_part[(size_t)RPAD*8];
static __device__ float g_mu[RPAD];
static __device__ float g_rs[RPAD];
static __device__ float g_pre[NKEY*DD];
static __device__ int g_key[NROW];
static __device__ int g_rankloc[NROW];
static __device__ int g_histblk[NBLK*NKEY];
static __device__ int g_cnt[NKEY];
static __device__ int g_keystart[NKEY];
static __device__ int g_pstart[EE+1];
static __device__ int g_c2o[RPAD];

// ------------------------ helpers ------------------------
__device__ __forceinline__ float gelu_exact(float v) {
    return 0.5f * v * (1.0f + erff(v * 0.7071067811865475f));
}
__device__ __forceinline__ void ldsm4u(uint32_t* r, uint32_t a) {
    asm volatile("ldmatrix.sync.aligned.m8n8.x4.shared.b16 {%0,%1,%2,%3},[%4];"
                 : "=r"(r[0]), "=r"(r[1]), "=r"(r[2]), "=r"(r[3]) : "r"(a));
}
__device__ __forceinline__ void ldsm4tu(uint32_t* r, uint32_t a) {
    asm volatile("ldmatrix.sync.aligned.m8n8.x4.trans.shared.b16 {%0,%1,%2,%3},[%4];"
                 : "=r"(r[0]), "=r"(r[1]), "=r"(r[2]), "=r"(r[3]) : "r"(a));
}
__device__ __forceinline__ void mma16816(float* c, const uint32_t* a, const uint32_t* b) {
    asm volatile(
        "mma.sync.aligned.m16n8k16.row.col.f32.f16.f16.f32 "
        "{%0,%1,%2,%3},{%4,%5,%6,%7},{%8,%9},{%0,%1,%2,%3};"
        : "+f"(c[0]), "+f"(c[1]), "+f"(c[2]), "+f"(c[3])
        : "r"(a[0]), "r"(a[1]), "r"(a[2]), "r"(a[3]), "r"(b[0]), "r"(b[1]));
}
__device__ __forceinline__ void lds128f(float4& f, uint32_t a) {
    asm volatile("ld.shared.v4.f32 {%0,%1,%2,%3},[%4];"
                 : "=f"(f.x), "=f"(f.y), "=f"(f.z), "=f"(f.w) : "r"(a));
}
__device__ __forceinline__ void sts128u(uint32_t a, uint32_t x, uint32_t y, uint32_t z, uint32_t w) {
    asm volatile("st.shared.v4.b32 [%0],{%1,%2,%3,%4};" :: "r"(a), "r"(x), "r"(y), "r"(z), "r"(w));
}
#define CP16U(saddr, gptr) asm volatile("cp.async.cg.shared.global [%0],[%1],16;" :: "r"(saddr), "l"(gptr))

__device__ __forceinline__ float bsum(float v, float* red, int nw) {
    int lane = threadIdx.x & 31, w = threadIdx.x >> 5;
    #pragma unroll
    for (int o = 16; o; o >>= 1) v += __shfl_xor_sync(0xffffffffu, v, o);
    if (lane == 0) red[w] = v;
    __syncthreads();
    float r = 0.f;
    for (int i = 0; i < nw; i++) r += red[i];
    __syncthreads();
    return r;
}

// ------------------------ K0: gate + per-block stable rank + histogram ------------------------
__global__ void __launch_bounds__(512) k_gatehist(const float* __restrict__ x,
                                                  const float* __restrict__ Wg,
                                                  const float* __restrict__ bg) {
    __shared__ int keys[128];
    __shared__ int cnt[NKEY];
    int t = threadIdx.x, w = t >> 5, lane = t & 31;
    if (t < NKEY) cnt[t] = 0;

    #pragma unroll
    for (int it = 0; it < 4; it++) {
        int tl = it * 16 + w;
        int n  = blockIdx.x * 64 + tl;
        float s[8] = {0,0,0,0,0,0,0,0};
        for (int i = lane; i < DD; i += 32) {
            float xv = x[(size_t)n*DD + i];
            #pragma unroll
            for (int e = 0; e < 8; e++) s[e] += xv * Wg[i*8 + e];
        }
        #pragma unroll
        for (int e = 0; e < 8; e++)
            #pragma unroll
            for (int o = 16; o; o >>= 1) s[e] += __shfl_xor_sync(0xffffffffu, s[e], o);
        if (lane == 0) {
            float m = -1e30f;
            #pragma unroll
            for (int e = 0; e < 8; e++) { s[e] += bg[e]; m = fmaxf(m, s[e]); }
            float p[8], sum = 0.f;
            #pragma unroll
            for (int e = 0; e < 8; e++) { p[e] = expf(s[e] - m); sum += p[e]; }
            #pragma unroll
            for (int e = 0; e < 8; e++) p[e] /= sum;
            int e1 = 0;
            #pragma unroll
            for (int e = 1; e < 8; e++) if (p[e] > p[e1]) e1 = e;
            int e2 = -1;
            #pragma unroll
            for (int e = 0; e < 8; e++) if (e != e1 && (e2 < 0 || p[e] > p[e2])) e2 = e;
            int b = n >> 10;
            keys[2*tl]   = e1*8 + b;
            keys[2*tl+1] = e2*8 + b;
        }
    }
    __syncthreads();

    int k = (t < 128) ? keys[t] : 0;
    int myrank = 0;
    for (int ww = 0; ww < 4; ww++) {
        if (w == ww) {
            unsigned mask = __match_any_sync(0xffffffffu, k);
            unsigned lower = mask & ((1u << lane) - 1u);
            int leader = __ffs(mask) - 1;
            int base = 0;
            if (lane == leader) base = atomicAdd(&cnt[k], __popc(mask));
            base = __shfl_sync(mask, base, leader);
            myrank = base + __popc(lower);
        }
        __syncthreads();
    }
    if (t < 128) {
        int gr = blockIdx.x * 128 + t;
        g_key[gr] = k;
        g_rankloc[gr] = myrank;
    }
    if (t < NKEY) g_histblk[blockIdx.x * NKEY + t] = cnt[t];
}

// ------------------------ K1: scan (redundant per block) + scatter ------------------------
__global__ void __launch_bounds__(128) k_scanscatter() {
    __shared__ int cs[NKEY], koff[NKEY], sk[NKEY], sp_[EE+1];
    int t = threadIdx.x, j = blockIdx.x;
    if (t < NKEY) {
        int c = 0, off = 0;
        for (int blk = 0; blk < NBLK; blk++) {
            int h = g_histblk[blk*NKEY + t];
            if (blk < j) off += h;
            c += h;
        }
        cs[t] = c; koff[t] = off;
    }
    __syncthreads();
    if (t == 0) {
        int ps = 0;
        for (int e = 0; e < EE; e++) {
            sp_[e] = ps;
            int Re = 0;
            for (int b = 0; b < 8; b++) Re += cs[e*8 + b];
            ps += ((Re + 127) / 128) * 128;
        }
        sp_[EE] = ps;
        for (int e = 0; e < EE; e++) {
            int o = sp_[e];
            for (int b = 0; b < 8; b++) { sk[e*8+b] = o; o += cs[e*8+b]; }
        }
    }
    __syncthreads();
    int r = j*128 + t;
    int k = g_key[r];
    g_c2o[sk[k] + koff[k] + g_rankloc[r]] = r;
    if (j == 0) {
        if (t < NKEY) { g_cnt[t] = cs[t]; g_keystart[t] = sk[t]; }
        if (t < EE+1) g_pstart[t] = sp_[t];
        for (int e = 0; e < EE; e++) {
            int pe = sk[e*8+7] + cs[e*8+7];
            for (int p = pe + t; p < sp_[e+1]; p += 128) g_c2o[p] = -1;
        }
        for (int p = sp_[EE] + t; p < RPAD; p += 128) g_c2o[p] = -1;
    }
}

// ------------------------ K2: gather xg -> fp16 ------------------------
__global__ void k_gather(const float* __restrict__ x) {
    int p = blockIdx.x, t = threadIdx.x; // 256 threads
    int r = g_c2o[p];
    float4 v = make_float4(0.f, 0.f, 0.f, 0.f);
    if (r >= 0) {
        int n = r >> 1;
        v = ((const float4*)x)[n*256 + t];
    }
    size_t j = (size_t)p*256 + t;
    ((__half2*)g_ah)[j*2]   = __floats2half2_rn(v.x, v.y);
    ((__half2*)g_ah)[j*2+1] = __floats2half2_rn(v.z, v.w);
}

// ------------------------ K3/K4: fp16 GEMM 128x128, KD=64, fused fp32->fp16 weight convert ------------------------
__device__ __forceinline__ void load_stage(uint32_t smbase, int st, int kt,
    const __half* __restrict__ Ag, const float* __restrict__ Wsrc,
    int row0, int n0, int t)
{
    const int k0 = kt * 64;
    const uint32_t aB = smbase + (uint32_t)st * A_ST;
    const uint32_t b32 = smbase + B32_OFF;
    #pragma unroll
    for (int i = 0; i < 4; i++) {
        int c = t + i * 256;
        int row = c >> 3, k8 = (c & 7) * 8;
        CP16U(aB + row*144 + k8*2, Ag + (size_t)(row0 + row) * DD + k0 + k8);
    }
    #pragma unroll
    for (int i = 0; i < 8; i++) {
        int c = t + i * 256;
        int br = c >> 5, ch = c & 31;
        CP16U(b32 + br*528 + ch*16, Wsrc + (size_t)(k0 + br) * DD + n0 + ch*4);
    }
    asm volatile("cp.async.commit_group;" ::: "memory");
}

template<int PHASE>
__global__ void __launch_bounds__(256, 2) k_gemm(const float* __restrict__ bias,
                                                 const float* __restrict__ xsrc,
                                                 const float* __restrict__ Wsrc) {
    extern __shared__ char smraw[];
    __shared__ float2 sp[4][128];   // PHASE 2 partial stats

    const int t = threadIdx.x;
    const int row0 = blockIdx.x * 128;
    if (row0 >= g_pstart[EE]) return;
    int e = 0;
    while (row0 >= g_pstart[e+1]) e++;
    const int n0 = blockIdx.y * 128;
    const __half* Ag = (PHASE == 1) ? g_ah : g_hh;
    const float* Wx = Wsrc + (size_t)e * DD * DD;

    const int lane = t & 31, w = t >> 5;
    const int wm = w & 1, wn = w >> 1;
    const int lr = lane & 15, lc = (lane >> 4) * 8;

    const uint32_t smbase = (uint32_t)__cvta_generic_to_shared(smraw);
    const uint32_t aRel = (uint32_t)((wm*64 + lr) * 144 + lc*2);
    const uint32_t bRel = (uint32_t)(lr*272 + (wn*32 + lc)*2);
    // conversion indexing: 64 rows x 128 floats; thread t owns row t>>2, seg t&3 (32 floats = 128 B)
    const int crow = t >> 2, cseg = t & 3;
    const uint32_t cvtSrc = smbase + B32_OFF + crow*528 + cseg*128;
    const uint32_t cvtDstRel = (uint32_t)(crow*272 + cseg*64);

    float acc[4][4][4];
    #pragma unroll
    for (int i = 0; i < 4; i++)
        #pragma unroll
        for (int j = 0; j < 4; j++)
            #pragma unroll
            for (int q = 0; q < 4; q++) acc[i][j][q] = 0.f;

    load_stage(smbase, 0, 0, Ag, Wx, row0, n0, t);

    uint32_t af[2][4][4], bf[2][2][4];

    for (int kt = 0; kt < 16; kt++) {
        const int st = kt & 1;
        asm volatile("cp.async.wait_group 0;" ::: "memory");
        __syncthreads();                       // loads for kt landed; prior readers done

        // convert B32 (fp32, stage kt) -> registers as packed half2
        uint32_t h[16];
        #pragma unroll
        for (int i = 0; i < 8; i++) {
            float4 f;
            lds128f(f, cvtSrc + i*16);
            __half2 p0 = __floats2half2_rn(f.x, f.y);
            __half2 p1 = __floats2half2_rn(f.z, f.w);
            h[2*i]   = *(uint32_t*)&p0;
            h[2*i+1] = *(uint32_t*)&p1;
        }
        __syncthreads();                       // all B32 reads done; safe to refill

        if (kt + 1 < 16)
            load_stage(smbase, st ^ 1, kt + 1, Ag, Wx, row0, n0, t);

        // write fp16 B tile for this stage
        const uint32_t bB = smbase + B16_OFF + (uint32_t)st * B16_ST;
        #pragma unroll
        for (int jv = 0; jv < 4; jv++)
            sts128u(bB + cvtDstRel + jv*16, h[4*jv], h[4*jv+1], h[4*jv+2], h[4*jv+3]);
        __syncthreads();                       // B16[st] visible

        const uint32_t sbA = smbase + (uint32_t)st * A_ST;
        #pragma unroll
        for (int mt = 0; mt < 4; mt++) ldsm4u(af[0][mt], sbA + aRel + mt*(16*144));
        #pragma unroll
        for (int ng = 0; ng < 2; ng++) ldsm4tu(bf[0][ng], bB + bRel + ng*32);

        #pragma unroll
        for (int k16 = 0; k16 < 4; k16++) {
            const int cur = k16 & 1;
            if (k16 < 3) {
                const uint32_t ka = sbA + aRel + (k16+1)*32;
                const uint32_t kb = bB + bRel + (k16+1)*(16*272);
                #pragma unroll
                for (int mt = 0; mt < 4; mt++) ldsm4u(af[cur^1][mt], ka + mt*(16*144));
                #pragma unroll
                for (int ng = 0; ng < 2; ng++) ldsm4tu(bf[cur^1][ng], kb + ng*32);
            }
            #pragma unroll
            for (int mt = 0; mt < 4; mt++)
                #pragma unroll
                for (int ng = 0; ng < 2; ng++)
                    #pragma unroll
                    for (int hf = 0; hf < 2; hf++)
                        mma16816(acc[mt][ng*2 + hf], af[cur][mt], &bf[cur][ng][hf*2]);
        }
    }

    // epilogue (PHASE 2: residual rows straight from x, L2-resident)
    const float* xrow[4][2];
    if (PHASE == 2) {
        #pragma unroll
        for (int mt = 0; mt < 4; mt++)
            #pragma unroll
            for (int hf = 0; hf < 2; hf++) {
                int r2 = row0 + wm*64 + mt*16 + (lane >> 2) + hf*8;
                int rr = g_c2o[r2];
                xrow[mt][hf] = (rr >= 0) ? (xsrc + (size_t)(rr >> 1) * DD) : nullptr;
            }
    }

    float psum[4][2], psq[4][2];
    if (PHASE == 2) {
        #pragma unroll
        for (int mt = 0; mt < 4; mt++) { psum[mt][0]=psum[mt][1]=psq[mt][0]=psq[mt][1]=0.f; }
    }
    #pragma unroll
    for (int mt = 0; mt < 4; mt++)
        #pragma unroll
        for (int nt = 0; nt < 4; nt++) {
            int row = row0 + wm*64 + mt*16 + (lane >> 2);
            int col = n0 + wn*32 + nt*8 + (lane & 3)*2;
            #pragma unroll
            for (int hf = 0; hf < 2; hf++) {
                int r2 = row + hf*8;
                size_t gi = (size_t)r2*DD + col;
                float v0 = acc[mt][nt][hf*2 + 0];
                float v1 = acc[mt][nt][hf*2 + 1];
                float b0 = bias[e*DD + col], b1v = bias[e*DD + col + 1];
                if (PHASE == 1) {
                    v0 = gelu_exact(v0 + b0);
                    v1 = gelu_exact(v1 + b1v);
                    *(__half2*)(&g_hh[gi]) = __floats2half2_rn(v0, v1);
                } else {
                    float2 xg = make_float2(0.f, 0.f);
                    if (xrow[mt][hf]) xg = *(const float2*)&xrow[mt][hf][col];
                    float o0 = v0 + b0  + xg.x;
                    float o1 = v1 + b1v + xg.y;
                    float2 o; o.x = o0; o.y = o1;
                    *(float2*)(&g_y[gi]) = o;
                    psum[mt][hf] += o0 + o1;
                    psq[mt][hf]  += o0*o0 + o1*o1;
                }
            }
        }
    if (PHASE == 2) {
        #pragma unroll
        for (int mt = 0; mt < 4; mt++)
            #pragma unroll
            for (int hf = 0; hf < 2; hf++) {
                #pragma unroll
                for (int o = 1; o <= 2; o <<= 1) {
                    psum[mt][hf] += __shfl_xor_sync(0xffffffffu, psum[mt][hf], o);
                    psq[mt][hf]  += __shfl_xor_sync(0xffffffffu, psq[mt][hf], o);
                }
            }
        if ((lane & 3) == 0) {
            #pragma unroll
            for (int mt = 0; mt < 4; mt++)
                #pragma unroll
                for (int hf = 0; hf < 2; hf++) {
                    int lrow = wm*64 + mt*16 + (lane >> 2) + hf*8;
                    float2 v; v.x = psum[mt][hf]; v.y = psq[mt][hf];
                    sp[wn][lrow] = v;
                }
        }
        __syncthreads();
        if (t < 128) {
            float2 a0 = sp[0][t], a1 = sp[1][t], a2 = sp[2][t], a3 = sp[3][t];
            float2 r; r.x = ((a0.x + a1.x) + a2.x) + a3.x; r.y = ((a0.y + a1.y) + a2.y) + a3.y;
            g_part[(size_t)(row0 + t)*8 + blockIdx.y] = r;
        }
    }
}

// ------------------------ K5: LN stats from partials ------------------------
__global__ void k_stats() {
    int p = blockIdx.x * 256 + threadIdx.x;
    float s = 0.f, q = 0.f;
    #pragma unroll
    for (int i = 0; i < 8; i++) {
        float2 v = g_part[(size_t)p*8 + i];
        s += v.x; q += v.y;
    }
    float mu = s * (1.f/1024.f);
    float var = q * (1.f/1024.f) - mu*mu;
    g_mu[p] = mu;
    g_rs[p] = rsqrtf(fmaxf(var, 0.f) + 1e-5f);
}

// ------------------------ K6: deterministic segment reduction (4-way split) ------------------------
__global__ void __launch_bounds__(512) k_reduce(const float* __restrict__ lng,
                                                const float* __restrict__ lnb) {
    __shared__ float sp2[4][128];
    int k = blockIdx.x;
    int t = threadIdx.x;
    int dl = t & 127, chunk = t >> 7;
    int d = blockIdx.y * 128 + dl;
    int e = k >> 3, b = k & 7;
    int st = g_keystart[k], c = g_cnt[k];
    int i0 = (c * chunk) >> 2, i1 = (c * (chunk + 1)) >> 2;
    float s = 0.f;
    #pragma unroll 4
    for (int i = i0; i < i1; i++) {
        int p = st + i;
        s += (g_y[(size_t)p*DD + d] - g_mu[p]) * g_rs[p];
    }
    sp2[chunk][dl] = s;
    __syncthreads();
    if (chunk == 0) {
        float tot = ((sp2[0][dl] + sp2[1][dl]) + sp2[2][dl]) + sp2[3][dl];
        g_pre[(b*8 + e)*DD + d] = lng[e*DD + d] * tot + (float)c * lnb[e*DD + d];
    }
}

// ------------------------ K7: final LN ------------------------
__global__ void k_final(const float* __restrict__ gng, const float* __restrict__ gnb,
                        float* __restrict__ out) {
    __shared__ float red[8];
    int row = blockIdx.x, t = threadIdx.x;  // 256 threads
    float v[4];
    #pragma unroll
    for (int i = 0; i < 4; i++) v[i] = g_pre[row*DD + t + i*256];
    float s = 0.f;
    #pragma unroll
    for (int i = 0; i < 4; i++) s += v[i];
    s = bsum(s, red, 8);
    float mu = s * (1.f/1024.f);
    float q = 0.f;
    #pragma unroll
    for (int i = 0; i < 4; i++) { float d = v[i] - mu; q += d*d; }
    q = bsum(q, red, 8);
    float rs = rsqrtf(q*(1.f/1024.f) + 1e-5f);
    #pragma unroll
    for (int i = 0; i < 4; i++) {
        int d = t + i*256;
        out[row*DD + d] = (v[i] - mu) * rs * gng[d] + gnb[d];
    }
}

// ------------------------ launch ------------------------
extern "C" void kernel_launch(void* const* d_in, const int* in_sizes, int n_in,
                              void* d_out, int out_size) {
    const float* x     = (const float*)d_in[0];
    const float* Wg    = (const float*)d_in[2];
    const float* bg    = (const float*)d_in[3];
    const float* W1    = (const float*)d_in[4];
    const float* b1    = (const float*)d_in[5];
    const float* W2    = (const float*)d_in[6];
    const float* b2    = (const float*)d_in[7];
    const float* lng   = (const float*)d_in[8];
    const float* lnb   = (const float*)d_in[9];
    const float* gng   = (const float*)d_in[10];
    const float* gnb   = (const float*)d_in[11];
    float* out = (float*)d_out;

    cudaFuncSetAttribute(k_gemm<1>, cudaFuncAttributeMaxDynamicSharedMemorySize, GEMM_SMEM);
    cudaFuncSetAttribute(k_gemm<2>, cudaFuncAttributeMaxDynamicSharedMemorySize, GEMM_SMEM);

    k_gatehist<<<NBLK, 512>>>(x, Wg, bg);                           // 0
    k_scanscatter<<<NBLK, 128>>>();                                 // 1
    k_gather<<<RPAD, 256>>>(x);                                     // 2
    k_gemm<1><<<dim3(RPAD/128, 8), 256, GEMM_SMEM>>>(b1, x, W1);    // 3  <- profiled launch
    k_gemm<2><<<dim3(RPAD/128, 8), 256, GEMM_SMEM>>>(b2, x, W2);    // 4
    k_stats<<<RPAD/256, 256>>>();                                   // 5
    k_reduce<<<dim3(NKEY, 8), 512>>>(lng, lnb);                     // 6
    k_final<<<NKEY, 256>>>(gng, gnb, out);                          // 7
}

// round 15
// speedup vs baseline: 1.2660x; 1.2660x over previous
#include <cuda_runtime.h>
#include <cuda_fp16.h>
#include <math.h>
#include <stdint.h>

#define DD 1024
#define EE 8
#define NTOK 8192
#define NROW 16384
#define RPAD 17408
#define NKEY 64
#define NBLK 128
#define CVTBLK 8192
#define APAD 72
#define STAGE_A (128*APAD*2)
#define STAGE_B (64*136*2)
#define STAGE_BYTES (STAGE_A + STAGE_B)
#define GEMM_SMEM (2*STAGE_BYTES)

// ------------------------ scratch (device globals) ------------------------
static __device__ __align__(256) __half g_w1[(size_t)EE*DD*DD];   // fp16 [e][k][n]
static __device__ __align__(256) __half g_w2[(size_t)EE*DD*DD];   // fp16 [e][k][n]
static __device__ __align__(256) __half g_ah[(size_t)RPAD*DD];    // fp16 xg
static __device__ __align__(256) __half g_hh[(size_t)RPAD*DD];    // fp16 gelu(h)
static __device__ __align__(256) __half g_yh[(size_t)RPAD*DD];    // fp16 y (gemm2 out)
static __device__ __align__(256) float2 g_part[(size_t)RPAD*8];
static __device__ float g_mu[RPAD];
static __device__ float g_rs[RPAD];
static __device__ float g_pre[NKEY*DD];
static __device__ int g_key[NROW];
static __device__ int g_rankloc[NROW];
static __device__ int g_histblk[NBLK*NKEY];
static __device__ int g_cnt[NKEY];
static __device__ int g_keystart[NKEY];
static __device__ int g_pstart[EE+1];
static __device__ int g_c2o[RPAD];

// ------------------------ helpers ------------------------
__device__ __forceinline__ float gelu_exact(float v) {
    return 0.5f * v * (1.0f + erff(v * 0.7071067811865475f));
}
__device__ __forceinline__ void ldsm4u(uint32_t* r, uint32_t a) {
    asm volatile("ldmatrix.sync.aligned.m8n8.x4.shared.b16 {%0,%1,%2,%3},[%4];"
                 : "=r"(r[0]), "=r"(r[1]), "=r"(r[2]), "=r"(r[3]) : "r"(a));
}
__device__ __forceinline__ void ldsm4tu(uint32_t* r, uint32_t a) {
    asm volatile("ldmatrix.sync.aligned.m8n8.x4.trans.shared.b16 {%0,%1,%2,%3},[%4];"
                 : "=r"(r[0]), "=r"(r[1]), "=r"(r[2]), "=r"(r[3]) : "r"(a));
}
__device__ __forceinline__ void mma16816(float* c, const uint32_t* a, const uint32_t* b) {
    asm volatile(
        "mma.sync.aligned.m16n8k16.row.col.f32.f16.f16.f32 "
        "{%0,%1,%2,%3},{%4,%5,%6,%7},{%8,%9},{%0,%1,%2,%3};"
        : "+f"(c[0]), "+f"(c[1]), "+f"(c[2]), "+f"(c[3])
        : "r"(a[0]), "r"(a[1]), "r"(a[2]), "r"(a[3]), "r"(b[0]), "r"(b[1]));
}
#define CP16U(saddr, gptr) asm volatile("cp.async.cg.shared.global [%0],[%1],16;" :: "r"(saddr), "l"(gptr))

__device__ __forceinline__ float bsum(float v, float* red, int nw) {
    int lane = threadIdx.x & 31, w = threadIdx.x >> 5;
    #pragma unroll
    for (int o = 16; o; o >>= 1) v += __shfl_xor_sync(0xffffffffu, v, o);
    if (lane == 0) red[w] = v;
    __syncthreads();
    float r = 0.f;
    for (int i = 0; i < nw; i++) r += red[i];
    __syncthreads();
    return r;
}

// ------------------------ K0: gate+hist blocks (0..127) and weight-convert blocks (128..) in ONE launch ------------------------
__global__ void __launch_bounds__(512) k_gatehist(const float* __restrict__ x,
                                                  const float* __restrict__ Wg,
                                                  const float* __restrict__ bg,
                                                  const float* __restrict__ W1,
                                                  const float* __restrict__ W2) {
    int t = threadIdx.x;
    if (blockIdx.x >= NBLK) {
        // streaming fp32->fp16 weight convert (overlaps the gate compute)
        const int T = EE*DD*DD/4;   // float4s per tensor
        int i = (blockIdx.x - NBLK) * 512 + t;
        const float* src; __half* dst; int q;
        if (i < T) { src = W1; dst = g_w1; q = i; }
        else       { src = W2; dst = g_w2; q = i - T; }
        float4 v = ((const float4*)src)[q];
        ((__half2*)dst)[q*2]   = __floats2half2_rn(v.x, v.y);
        ((__half2*)dst)[q*2+1] = __floats2half2_rn(v.z, v.w);
        return;
    }

    __shared__ int keys[128];
    __shared__ int cnt[NKEY];
    int w = t >> 5, lane = t & 31;
    if (t < NKEY) cnt[t] = 0;

    #pragma unroll
    for (int it = 0; it < 4; it++) {
        int tl = it * 16 + w;
        int n  = blockIdx.x * 64 + tl;
        float s[8] = {0,0,0,0,0,0,0,0};
        for (int i = lane; i < DD; i += 32) {
            float xv = x[(size_t)n*DD + i];
            #pragma unroll
            for (int e = 0; e < 8; e++) s[e] += xv * Wg[i*8 + e];
        }
        #pragma unroll
        for (int e = 0; e < 8; e++)
            #pragma unroll
            for (int o = 16; o; o >>= 1) s[e] += __shfl_xor_sync(0xffffffffu, s[e], o);
        if (lane == 0) {
            float m = -1e30f;
            #pragma unroll
            for (int e = 0; e < 8; e++) { s[e] += bg[e]; m = fmaxf(m, s[e]); }
            float p[8], sum = 0.f;
            #pragma unroll
            for (int e = 0; e < 8; e++) { p[e] = expf(s[e] - m); sum += p[e]; }
            #pragma unroll
            for (int e = 0; e < 8; e++) p[e] /= sum;
            int e1 = 0;
            #pragma unroll
            for (int e = 1; e < 8; e++) if (p[e] > p[e1]) e1 = e;
            int e2 = -1;
            #pragma unroll
            for (int e = 0; e < 8; e++) if (e != e1 && (e2 < 0 || p[e] > p[e2])) e2 = e;
            int b = n >> 10;
            keys[2*tl]   = e1*8 + b;
            keys[2*tl+1] = e2*8 + b;
        }
    }
    __syncthreads();

    int k = (t < 128) ? keys[t] : 0;
    int myrank = 0;
    for (int ww = 0; ww < 4; ww++) {
        if (w == ww) {
            unsigned mask = __match_any_sync(0xffffffffu, k);
            unsigned lower = mask & ((1u << lane) - 1u);
            int leader = __ffs(mask) - 1;
            int base = 0;
            if (lane == leader) base = atomicAdd(&cnt[k], __popc(mask));
            base = __shfl_sync(mask, base, leader);
            myrank = base + __popc(lower);
        }
        __syncthreads();
    }
    if (t < 128) {
        int gr = blockIdx.x * 128 + t;
        g_key[gr] = k;
        g_rankloc[gr] = myrank;
    }
    if (t < NKEY) g_histblk[blockIdx.x * NKEY + t] = cnt[t];
}

// ------------------------ K1: scan (redundant per block) + scatter ------------------------
__global__ void __launch_bounds__(128) k_scanscatter() {
    __shared__ int cs[NKEY], koff[NKEY], sk[NKEY], sp_[EE+1];
    int t = threadIdx.x, j = blockIdx.x;
    if (t < NKEY) {
        int c = 0, off = 0;
        for (int blk = 0; blk < NBLK; blk++) {
            int h = g_histblk[blk*NKEY + t];
            if (blk < j) off += h;
            c += h;
        }
        cs[t] = c; koff[t] = off;
    }
    __syncthreads();
    if (t == 0) {
        int ps = 0;
        for (int e = 0; e < EE; e++) {
            sp_[e] = ps;
            int Re = 0;
            for (int b = 0; b < 8; b++) Re += cs[e*8 + b];
            ps += ((Re + 127) / 128) * 128;
        }
        sp_[EE] = ps;
        for (int e = 0; e < EE; e++) {
            int o = sp_[e];
            for (int b = 0; b < 8; b++) { sk[e*8+b] = o; o += cs[e*8+b]; }
        }
    }
    __syncthreads();
    int r = j*128 + t;
    int k = g_key[r];
    g_c2o[sk[k] + koff[k] + g_rankloc[r]] = r;
    if (j == 0) {
        if (t < NKEY) { g_cnt[t] = cs[t]; g_keystart[t] = sk[t]; }
        if (t < EE+1) g_pstart[t] = sp_[t];
        for (int e = 0; e < EE; e++) {
            int pe = sk[e*8+7] + cs[e*8+7];
            for (int p = pe + t; p < sp_[e+1]; p += 128) g_c2o[p] = -1;
        }
        for (int p = sp_[EE] + t; p < RPAD; p += 128) g_c2o[p] = -1;
    }
}

// ------------------------ K2: gather xg -> fp16 ------------------------
__global__ void k_gather(const float* __restrict__ x) {
    int p = blockIdx.x, t = threadIdx.x; // 256 threads
    int r = g_c2o[p];
    float4 v = make_float4(0.f, 0.f, 0.f, 0.f);
    if (r >= 0) {
        int n = r >> 1;
        v = ((const float4*)x)[n*256 + t];
    }
    size_t j = (size_t)p*256 + t;
    ((__half2*)g_ah)[j*2]   = __floats2half2_rn(v.x, v.y);
    ((__half2*)g_ah)[j*2+1] = __floats2half2_rn(v.z, v.w);
}

// ------------------------ K3/K4: fp16 GEMM 128x128, KD=64, 2-stage, reg-prefetched (R12) ------------------------
__device__ __forceinline__ void load_stage(uint32_t smbase, int st, int kt,
    const __half* __restrict__ Ag, const __half* __restrict__ Bw,
    int row0, int n0, int t)
{
    const int k0 = kt * 64;
    const uint32_t sb = smbase + (uint32_t)st * STAGE_BYTES;
    #pragma unroll
    for (int i = 0; i < 4; i++) {
        int c = t + i * 256;
        int row = c >> 3, k8 = (c & 7) * 8;
        CP16U(sb + row*(APAD*2) + k8*2, Ag + (size_t)(row0 + row) * DD + k0 + k8);
    }
    #pragma unroll
    for (int i = 0; i < 4; i++) {
        int c = t + i * 256;
        int br = c >> 4, bc = (c & 15) * 8;
        CP16U(sb + STAGE_A + br*272 + bc*2, Bw + (size_t)(k0 + br) * DD + n0 + bc);
    }
    asm volatile("cp.async.commit_group;" ::: "memory");
}

template<int PHASE>
__global__ void __launch_bounds__(256, 2) k_gemm(const float* __restrict__ bias,
                                                 const float* __restrict__ xsrc) {
    extern __shared__ char smraw[];
    __shared__ float2 sp[4][128];   // PHASE 2 partial stats

    const int t = threadIdx.x;
    const int row0 = blockIdx.x * 128;
    if (row0 >= g_pstart[EE]) return;
    int e = 0;
    while (row0 >= g_pstart[e+1]) e++;
    const int n0 = blockIdx.y * 128;
    const __half* Ag = (PHASE == 1) ? g_ah : g_hh;
    const __half* Bw = ((PHASE == 1) ? g_w1 : g_w2) + (size_t)e*DD*DD;

    const int lane = t & 31, w = t >> 5;
    const int wm = w & 1, wn = w >> 1;
    const int lr = lane & 15, lc = (lane >> 4) * 8;

    const uint32_t smbase = (uint32_t)__cvta_generic_to_shared(smraw);
    const uint32_t aRel = (uint32_t)((wm*64 + lr) * (APAD*2) + lc*2);
    const uint32_t bRel = (uint32_t)(STAGE_A + lr*272 + (wn*32 + lc)*2);

    float acc[4][4][4];
    #pragma unroll
    for (int i = 0; i < 4; i++)
        #pragma unroll
        for (int j = 0; j < 4; j++)
            #pragma unroll
            for (int q = 0; q < 4; q++) acc[i][j][q] = 0.f;

    load_stage(smbase, 0, 0, Ag, Bw, row0, n0, t);

    uint32_t af[2][4][4], bf[2][2][4];

    for (int kt = 0; kt < 16; kt++) {
        const int st = kt & 1;
        __syncthreads();
        if (kt + 1 < 16) {
            load_stage(smbase, st ^ 1, kt + 1, Ag, Bw, row0, n0, t);
            asm volatile("cp.async.wait_group 1;" ::: "memory");
        } else {
            asm volatile("cp.async.wait_group 0;" ::: "memory");
        }
        __syncthreads();

        const uint32_t sb = smbase + (uint32_t)st * STAGE_BYTES;
        #pragma unroll
        for (int mt = 0; mt < 4; mt++) ldsm4u(af[0][mt], sb + aRel + mt*(16*APAD*2));
        #pragma unroll
        for (int ng = 0; ng < 2; ng++) ldsm4tu(bf[0][ng], sb + bRel + ng*32);

        #pragma unroll
        for (int k16 = 0; k16 < 4; k16++) {
            const int cur = k16 & 1;
            if (k16 < 3) {
                const uint32_t ka = sb + aRel + (k16+1)*32;
                const uint32_t kb = sb + bRel + (k16+1)*(16*272);
                #pragma unroll
                for (int mt = 0; mt < 4; mt++) ldsm4u(af[cur^1][mt], ka + mt*(16*APAD*2));
                #pragma unroll
                for (int ng = 0; ng < 2; ng++) ldsm4tu(bf[cur^1][ng], kb + ng*32);
            }
            #pragma unroll
            for (int mt = 0; mt < 4; mt++)
                #pragma unroll
                for (int ng = 0; ng < 2; ng++)
                    #pragma unroll
                    for (int hf = 0; hf < 2; hf++)
                        mma16816(acc[mt][ng*2 + hf], af[cur][mt], &bf[cur][ng][hf*2]);
        }
    }

    // epilogue (PHASE 2: residual rows straight from x, L2-resident)
    const float* xrow[4][2];
    if (PHASE == 2) {
        #pragma unroll
        for (int mt = 0; mt < 4; mt++)
            #pragma unroll
            for (int hf = 0; hf < 2; hf++) {
                int r2 = row0 + wm*64 + mt*16 + (lane >> 2) + hf*8;
                int rr = g_c2o[r2];
                xrow[mt][hf] = (rr >= 0) ? (xsrc + (size_t)(rr >> 1) * DD) : nullptr;
            }
    }

    float psum[4][2], psq[4][2];
    if (PHASE == 2) {
        #pragma unroll
        for (int mt = 0; mt < 4; mt++) { psum[mt][0]=psum[mt][1]=psq[mt][0]=psq[mt][1]=0.f; }
    }
    #pragma unroll
    for (int mt = 0; mt < 4; mt++)
        #pragma unroll
        for (int nt = 0; nt < 4; nt++) {
            int row = row0 + wm*64 + mt*16 + (lane >> 2);
            int col = n0 + wn*32 + nt*8 + (lane & 3)*2;
            #pragma unroll
            for (int hf = 0; hf < 2; hf++) {
                int r2 = row + hf*8;
                size_t gi = (size_t)r2*DD + col;
                float v0 = acc[mt][nt][hf*2 + 0];
                float v1 = acc[mt][nt][hf*2 + 1];
                float b0 = bias[e*DD + col], b1v = bias[e*DD + col + 1];
                if (PHASE == 1) {
                    v0 = gelu_exact(v0 + b0);
                    v1 = gelu_exact(v1 + b1v);
                    *(__half2*)(&g_hh[gi]) = __floats2half2_rn(v0, v1);
                } else {
                    float2 xg = make_float2(0.f, 0.f);
                    if (xrow[mt][hf]) xg = *(const float2*)&xrow[mt][hf][col];
                    float o0 = v0 + b0  + xg.x;
                    float o1 = v1 + b1v + xg.y;
                    __half2 h2 = __floats2half2_rn(o0, o1);
                    *(__half2*)(&g_yh[gi]) = h2;
                    // stats from the ROUNDED values (self-consistent LN of stored y)
                    float o0r = __half2float(__low2half(h2));
                    float o1r = __half2float(__high2half(h2));
                    psum[mt][hf] += o0r + o1r;
                    psq[mt][hf]  += o0r*o0r + o1r*o1r;
                }
            }
        }
    if (PHASE == 2) {
        #pragma unroll
        for (int mt = 0; mt < 4; mt++)
            #pragma unroll
            for (int hf = 0; hf < 2; hf++) {
                #pragma unroll
                for (int o = 1; o <= 2; o <<= 1) {
                    psum[mt][hf] += __shfl_xor_sync(0xffffffffu, psum[mt][hf], o);
                    psq[mt][hf]  += __shfl_xor_sync(0xffffffffu, psq[mt][hf], o);
                }
            }
        if ((lane & 3) == 0) {
            #pragma unroll
            for (int mt = 0; mt < 4; mt++)
                #pragma unroll
                for (int hf = 0; hf < 2; hf++) {
                    int lrow = wm*64 + mt*16 + (lane >> 2) + hf*8;
                    float2 v; v.x = psum[mt][hf]; v.y = psq[mt][hf];
                    sp[wn][lrow] = v;
                }
        }
        __syncthreads();
        if (t < 128) {
            float2 a0 = sp[0][t], a1 = sp[1][t], a2 = sp[2][t], a3 = sp[3][t];
            float2 r; r.x = ((a0.x + a1.x) + a2.x) + a3.x; r.y = ((a0.y + a1.y) + a2.y) + a3.y;
            g_part[(size_t)(row0 + t)*8 + blockIdx.y] = r;
        }
    }
}

// ------------------------ K5: LN stats from partials ------------------------
__global__ void k_stats() {
    int p = blockIdx.x * 256 + threadIdx.x;
    float s = 0.f, q = 0.f;
    #pragma unroll
    for (int i = 0; i < 8; i++) {
        float2 v = g_part[(size_t)p*8 + i];
        s += v.x; q += v.y;
    }
    float mu = s * (1.f/1024.f);
    float var = q * (1.f/1024.f) - mu*mu;
    g_mu[p] = mu;
    g_rs[p] = rsqrtf(fmaxf(var, 0.f) + 1e-5f);
}

// ------------------------ K6: deterministic segment reduction (4-way split, fp16 y) ------------------------
__global__ void __launch_bounds__(512) k_reduce(const float* __restrict__ lng,
                                                const float* __restrict__ lnb) {
    __shared__ float sp2[4][128];
    int k = blockIdx.x;
    int t = threadIdx.x;
    int dl = t & 127, chunk = t >> 7;
    int d = blockIdx.y * 128 + dl;
    int e = k >> 3, b = k & 7;
    int st = g_keystart[k], c = g_cnt[k];
    int i0 = (c * chunk) >> 2, i1 = (c * (chunk + 1)) >> 2;
    float s = 0.f;
    #pragma unroll 4
    for (int i = i0; i < i1; i++) {
        int p = st + i;
        s += (__half2float(g_yh[(size_t)p*DD + d]) - g_mu[p]) * g_rs[p];
    }
    sp2[chunk][dl] = s;
    __syncthreads();
    if (chunk == 0) {
        float tot = ((sp2[0][dl] + sp2[1][dl]) + sp2[2][dl]) + sp2[3][dl];
        g_pre[(b*8 + e)*DD + d] = lng[e*DD + d] * tot + (float)c * lnb[e*DD + d];
    }
}

// ------------------------ K7: final LN ------------------------
__global__ void k_final(const float* __restrict__ gng, const float* __restrict__ gnb,
                        float* __restrict__ out) {
    __shared__ float red[8];
    int row = blockIdx.x, t = threadIdx.x;  // 256 threads
    float v[4];
    #pragma unroll
    for (int i = 0; i < 4; i++) v[i] = g_pre[row*DD + t + i*256];
    float s = 0.f;
    #pragma unroll
    for (int i = 0; i < 4; i++) s += v[i];
    s = bsum(s, red, 8);
    float mu = s * (1.f/1024.f);
    float q = 0.f;
    #pragma unroll
    for (int i = 0; i < 4; i++) { float d = v[i] - mu; q += d*d; }
    q = bsum(q, red, 8);
    float rs = rsqrtf(q*(1.f/1024.f) + 1e-5f);
    #pragma unroll
    for (int i = 0; i < 4; i++) {
        int d = t + i*256;
        out[row*DD + d] = (v[i] - mu) * rs * gng[d] + gnb[d];
    }
}

// ------------------------ launch ------------------------
extern "C" void kernel_launch(void* const* d_in, const int* in_sizes, int n_in,
                              void* d_out, int out_size) {
    const float* x     = (const float*)d_in[0];
    const float* Wg    = (const float*)d_in[2];
    const float* bg    = (const float*)d_in[3];
    const float* W1    = (const float*)d_in[4];
    const float* b1    = (const float*)d_in[5];
    const float* W2    = (const float*)d_in[6];
    const float* b2    = (const float*)d_in[7];
    const float* lng   = (const float*)d_in[8];
    const float* lnb   = (const float*)d_in[9];
    const float* gng   = (const float*)d_in[10];
    const float* gnb   = (const float*)d_in[11];
    float* out = (float*)d_out;

    cudaFuncSetAttribute(k_gemm<1>, cudaFuncAttributeMaxDynamicSharedMemorySize, GEMM_SMEM);
    cudaFuncSetAttribute(k_gemm<2>, cudaFuncAttributeMaxDynamicSharedMemorySize, GEMM_SMEM);

    k_gatehist<<<NBLK + CVTBLK, 512>>>(x, Wg, bg, W1, W2);        // 0 (gate ∥ weight convert)
    k_scanscatter<<<NBLK, 128>>>();                               // 1
    k_gather<<<RPAD, 256>>>(x);                                   // 2
    k_gemm<1><<<dim3(RPAD/128, 8), 256, GEMM_SMEM>>>(b1, x);      // 3  <- profiled launch
    k_gemm<2><<<dim3(RPAD/128, 8), 256, GEMM_SMEM>>>(b2, x);      // 4
    k_stats<<<RPAD/256, 256>>>();                                 // 5
    k_reduce<<<dim3(NKEY, 8), 512>>>(lng, lnb);                   // 6
    k_final<<<NKEY, 256>>>(gng, gnb, out);                        // 7
}

// round 16
// speedup vs baseline: 1.4343x; 1.1329x over previous
#include <cuda_runtime.h>
#include <cuda_fp16.h>
#include <math.h>
#include <stdint.h>

#define DD 1024
#define EE 8
#define NTOK 8192
#define NROW 16384
#define RPAD 17408
#define NKEY 64
#define NBLK 128
#define APAD 72
#define STAGE_A (128*APAD*2)
#define STAGE_B (64*136*2)
#define STAGE_BYTES (STAGE_A + STAGE_B)
#define GEMM_SMEM (2*STAGE_BYTES)

// ------------------------ scratch (device globals) ------------------------
static __device__ __align__(256) __half g_w1[(size_t)EE*DD*DD];   // fp16 [e][k][n]
static __device__ __align__(256) __half g_w2[(size_t)EE*DD*DD];   // fp16 [e][k][n]
static __device__ __align__(256) __half g_ah[(size_t)RPAD*DD];    // fp16 xg
static __device__ __align__(256) __half g_hh[(size_t)RPAD*DD];    // fp16 gelu(h)
static __device__ __align__(256) __half g_yh[(size_t)RPAD*DD];    // fp16 y (gemm2 out)
static __device__ __align__(256) float2 g_part[(size_t)RPAD*8];
static __device__ float g_mu[RPAD];
static __device__ float g_rs[RPAD];
static __device__ float g_pre[NKEY*DD];
static __device__ int g_key[NROW];
static __device__ int g_rankloc[NROW];
static __device__ int g_histblk[NBLK*NKEY];
static __device__ int g_cnt[NKEY];
static __device__ int g_keystart[NKEY];
static __device__ int g_pstart[EE+1];
static __device__ int g_c2o[RPAD];

// ------------------------ helpers ------------------------
__device__ __forceinline__ float gelu_exact(float v) {
    return 0.5f * v * (1.0f + erff(v * 0.7071067811865475f));
}
__device__ __forceinline__ void ldsm4u(uint32_t* r, uint32_t a) {
    asm volatile("ldmatrix.sync.aligned.m8n8.x4.shared.b16 {%0,%1,%2,%3},[%4];"
                 : "=r"(r[0]), "=r"(r[1]), "=r"(r[2]), "=r"(r[3]) : "r"(a));
}
__device__ __forceinline__ void ldsm4tu(uint32_t* r, uint32_t a) {
    asm volatile("ldmatrix.sync.aligned.m8n8.x4.trans.shared.b16 {%0,%1,%2,%3},[%4];"
                 : "=r"(r[0]), "=r"(r[1]), "=r"(r[2]), "=r"(r[3]) : "r"(a));
}
__device__ __forceinline__ void mma16816(float* c, const uint32_t* a, const uint32_t* b) {
    asm volatile(
        "mma.sync.aligned.m16n8k16.row.col.f32.f16.f16.f32 "
        "{%0,%1,%2,%3},{%4,%5,%6,%7},{%8,%9},{%0,%1,%2,%3};"
        : "+f"(c[0]), "+f"(c[1]), "+f"(c[2]), "+f"(c[3])
        : "r"(a[0]), "r"(a[1]), "r"(a[2]), "r"(a[3]), "r"(b[0]), "r"(b[1]));
}
#define CP16U(saddr, gptr) asm volatile("cp.async.cg.shared.global [%0],[%1],16;" :: "r"(saddr), "l"(gptr))

__device__ __forceinline__ float bsum(float v, float* red, int nw) {
    int lane = threadIdx.x & 31, w = threadIdx.x >> 5;
    #pragma unroll
    for (int o = 16; o; o >>= 1) v += __shfl_xor_sync(0xffffffffu, v, o);
    if (lane == 0) red[w] = v;
    __syncthreads();
    float r = 0.f;
    for (int i = 0; i < nw; i++) r += red[i];
    __syncthreads();
    return r;
}

// ------------------------ K0: gate + per-block stable rank + histogram ------------------------
__global__ void __launch_bounds__(512) k_gatehist(const float* __restrict__ x,
                                                  const float* __restrict__ Wg,
                                                  const float* __restrict__ bg) {
    __shared__ int keys[128];
    __shared__ int cnt[NKEY];
    int t = threadIdx.x, w = t >> 5, lane = t & 31;
    if (t < NKEY) cnt[t] = 0;

    #pragma unroll
    for (int it = 0; it < 4; it++) {
        int tl = it * 16 + w;
        int n  = blockIdx.x * 64 + tl;
        float s[8] = {0,0,0,0,0,0,0,0};
        for (int i = lane; i < DD; i += 32) {
            float xv = x[(size_t)n*DD + i];
            #pragma unroll
            for (int e = 0; e < 8; e++) s[e] += xv * Wg[i*8 + e];
        }
        #pragma unroll
        for (int e = 0; e < 8; e++)
            #pragma unroll
            for (int o = 16; o; o >>= 1) s[e] += __shfl_xor_sync(0xffffffffu, s[e], o);
        if (lane == 0) {
            float m = -1e30f;
            #pragma unroll
            for (int e = 0; e < 8; e++) { s[e] += bg[e]; m = fmaxf(m, s[e]); }
            float p[8], sum = 0.f;
            #pragma unroll
            for (int e = 0; e < 8; e++) { p[e] = expf(s[e] - m); sum += p[e]; }
            #pragma unroll
            for (int e = 0; e < 8; e++) p[e] /= sum;
            int e1 = 0;
            #pragma unroll
            for (int e = 1; e < 8; e++) if (p[e] > p[e1]) e1 = e;
            int e2 = -1;
            #pragma unroll
            for (int e = 0; e < 8; e++) if (e != e1 && (e2 < 0 || p[e] > p[e2])) e2 = e;
            int b = n >> 10;
            keys[2*tl]   = e1*8 + b;
            keys[2*tl+1] = e2*8 + b;
        }
    }
    __syncthreads();

    int k = (t < 128) ? keys[t] : 0;
    int myrank = 0;
    for (int ww = 0; ww < 4; ww++) {
        if (w == ww) {
            unsigned mask = __match_any_sync(0xffffffffu, k);
            unsigned lower = mask & ((1u << lane) - 1u);
            int leader = __ffs(mask) - 1;
            int base = 0;
            if (lane == leader) base = atomicAdd(&cnt[k], __popc(mask));
            base = __shfl_sync(mask, base, leader);
            myrank = base + __popc(lower);
        }
        __syncthreads();
    }
    if (t < 128) {
        int gr = blockIdx.x * 128 + t;
        g_key[gr] = k;
        g_rankloc[gr] = myrank;
    }
    if (t < NKEY) g_histblk[blockIdx.x * NKEY + t] = cnt[t];
}

// ------------------------ K1: scan (redundant per block) + scatter ------------------------
__global__ void __launch_bounds__(128) k_scanscatter() {
    __shared__ int cs[NKEY], koff[NKEY], sk[NKEY], sp_[EE+1];
    int t = threadIdx.x, j = blockIdx.x;
    if (t < NKEY) {
        int c = 0, off = 0;
        for (int blk = 0; blk < NBLK; blk++) {
            int h = g_histblk[blk*NKEY + t];
            if (blk < j) off += h;
            c += h;
        }
        cs[t] = c; koff[t] = off;
    }
    __syncthreads();
    if (t == 0) {
        int ps = 0;
        for (int e = 0; e < EE; e++) {
            sp_[e] = ps;
            int Re = 0;
            for (int b = 0; b < 8; b++) Re += cs[e*8 + b];
            ps += ((Re + 127) / 128) * 128;
        }
        sp_[EE] = ps;
        for (int e = 0; e < EE; e++) {
            int o = sp_[e];
            for (int b = 0; b < 8; b++) { sk[e*8+b] = o; o += cs[e*8+b]; }
        }
    }
    __syncthreads();
    int r = j*128 + t;
    int k = g_key[r];
    g_c2o[sk[k] + koff[k] + g_rankloc[r]] = r;
    if (j == 0) {
        if (t < NKEY) { g_cnt[t] = cs[t]; g_keystart[t] = sk[t]; }
        if (t < EE+1) g_pstart[t] = sp_[t];
        for (int e = 0; e < EE; e++) {
            int pe = sk[e*8+7] + cs[e*8+7];
            for (int p = pe + t; p < sp_[e+1]; p += 128) g_c2o[p] = -1;
        }
        for (int p = sp_[EE] + t; p < RPAD; p += 128) g_c2o[p] = -1;
    }
}

// ------------------------ K2: gather xg -> fp16 + weight convert (fused, R12) ------------------------
__global__ void k_gatherconvert(const float* __restrict__ x,
                                const float* __restrict__ W1, const float* __restrict__ W2) {
    int p = blockIdx.x, t = threadIdx.x; // 256 threads
    int r = g_c2o[p];
    float4 v = make_float4(0.f, 0.f, 0.f, 0.f);
    if (r >= 0) {
        int n = r >> 1;
        v = ((const float4*)x)[n*256 + t];
    }
    size_t j = (size_t)p*256 + t;
    ((__half2*)g_ah)[j*2]   = __floats2half2_rn(v.x, v.y);
    ((__half2*)g_ah)[j*2+1] = __floats2half2_rn(v.z, v.w);

    const int T = EE*DD*DD/4;
    int i = p*256 + t;
    if (i < 2*T) {
        const float* src; __half* dst; int q;
        if (i < T) { src = W1; dst = g_w1; q = i; }
        else       { src = W2; dst = g_w2; q = i - T; }
        float4 wv = ((const float4*)src)[q];
        ((__half2*)dst)[q*2]   = __floats2half2_rn(wv.x, wv.y);
        ((__half2*)dst)[q*2+1] = __floats2half2_rn(wv.z, wv.w);
    }
}

// ------------------------ K3/K4: fp16 GEMM 128x128, KD=64, 2-stage, reg-prefetched ------------------------
__device__ __forceinline__ void load_stage(uint32_t smbase, int st, int kt,
    const __half* __restrict__ Ag, const __half* __restrict__ Bw,
    int row0, int n0, int t)
{
    const int k0 = kt * 64;
    const uint32_t sb = smbase + (uint32_t)st * STAGE_BYTES;
    #pragma unroll
    for (int i = 0; i < 4; i++) {
        int c = t + i * 256;
        int row = c >> 3, k8 = (c & 7) * 8;
        CP16U(sb + row*(APAD*2) + k8*2, Ag + (size_t)(row0 + row) * DD + k0 + k8);
    }
    #pragma unroll
    for (int i = 0; i < 4; i++) {
        int c = t + i * 256;
        int br = c >> 4, bc = (c & 15) * 8;
        CP16U(sb + STAGE_A + br*272 + bc*2, Bw + (size_t)(k0 + br) * DD + n0 + bc);
    }
    asm volatile("cp.async.commit_group;" ::: "memory");
}

template<int PHASE>
__global__ void __launch_bounds__(256, 2) k_gemm(const float* __restrict__ bias,
                                                 const float* __restrict__ xsrc) {
    extern __shared__ char smraw[];
    __shared__ float2 sp[4][128];   // PHASE 2 partial stats

    const int t = threadIdx.x;
    const int row0 = blockIdx.x * 128;
    if (row0 >= g_pstart[EE]) return;
    int e = 0;
    while (row0 >= g_pstart[e+1]) e++;
    const int n0 = blockIdx.y * 128;
    const __half* Ag = (PHASE == 1) ? g_ah : g_hh;
    const __half* Bw = ((PHASE == 1) ? g_w1 : g_w2) + (size_t)e*DD*DD;

    const int lane = t & 31, w = t >> 5;
    const int wm = w & 1, wn = w >> 1;
    const int lr = lane & 15, lc = (lane >> 4) * 8;

    const uint32_t smbase = (uint32_t)__cvta_generic_to_shared(smraw);
    const uint32_t aRel = (uint32_t)((wm*64 + lr) * (APAD*2) + lc*2);
    const uint32_t bRel = (uint32_t)(STAGE_A + lr*272 + (wn*32 + lc)*2);

    float acc[4][4][4];
    #pragma unroll
    for (int i = 0; i < 4; i++)
        #pragma unroll
        for (int j = 0; j < 4; j++)
            #pragma unroll
            for (int q = 0; q < 4; q++) acc[i][j][q] = 0.f;

    load_stage(smbase, 0, 0, Ag, Bw, row0, n0, t);

    uint32_t af[2][4][4], bf[2][2][4];

    for (int kt = 0; kt < 16; kt++) {
        const int st = kt & 1;
        __syncthreads();
        if (kt + 1 < 16) {
            load_stage(smbase, st ^ 1, kt + 1, Ag, Bw, row0, n0, t);
            asm volatile("cp.async.wait_group 1;" ::: "memory");
        } else {
            asm volatile("cp.async.wait_group 0;" ::: "memory");
        }
        __syncthreads();

        const uint32_t sb = smbase + (uint32_t)st * STAGE_BYTES;
        #pragma unroll
        for (int mt = 0; mt < 4; mt++) ldsm4u(af[0][mt], sb + aRel + mt*(16*APAD*2));
        #pragma unroll
        for (int ng = 0; ng < 2; ng++) ldsm4tu(bf[0][ng], sb + bRel + ng*32);

        #pragma unroll
        for (int k16 = 0; k16 < 4; k16++) {
            const int cur = k16 & 1;
            if (k16 < 3) {
                const uint32_t ka = sb + aRel + (k16+1)*32;
                const uint32_t kb = sb + bRel + (k16+1)*(16*272);
                #pragma unroll
                for (int mt = 0; mt < 4; mt++) ldsm4u(af[cur^1][mt], ka + mt*(16*APAD*2));
                #pragma unroll
                for (int ng = 0; ng < 2; ng++) ldsm4tu(bf[cur^1][ng], kb + ng*32);
            }
            #pragma unroll
            for (int mt = 0; mt < 4; mt++)
                #pragma unroll
                for (int ng = 0; ng < 2; ng++)
                    #pragma unroll
                    for (int hf = 0; hf < 2; hf++)
                        mma16816(acc[mt][ng*2 + hf], af[cur][mt], &bf[cur][ng][hf*2]);
        }
    }

    // epilogue (PHASE 2: residual rows straight from x, L2-resident)
    const float* xrow[4][2];
    if (PHASE == 2) {
        #pragma unroll
        for (int mt = 0; mt < 4; mt++)
            #pragma unroll
            for (int hf = 0; hf < 2; hf++) {
                int r2 = row0 + wm*64 + mt*16 + (lane >> 2) + hf*8;
                int rr = g_c2o[r2];
                xrow[mt][hf] = (rr >= 0) ? (xsrc + (size_t)(rr >> 1) * DD) : nullptr;
            }
    }

    float psum[4][2], psq[4][2];
    if (PHASE == 2) {
        #pragma unroll
        for (int mt = 0; mt < 4; mt++) { psum[mt][0]=psum[mt][1]=psq[mt][0]=psq[mt][1]=0.f; }
    }
    #pragma unroll
    for (int mt = 0; mt < 4; mt++)
        #pragma unroll
        for (int nt = 0; nt < 4; nt++) {
            int row = row0 + wm*64 + mt*16 + (lane >> 2);
            int col = n0 + wn*32 + nt*8 + (lane & 3)*2;
            #pragma unroll
            for (int hf = 0; hf < 2; hf++) {
                int r2 = row + hf*8;
                size_t gi = (size_t)r2*DD + col;
                float v0 = acc[mt][nt][hf*2 + 0];
                float v1 = acc[mt][nt][hf*2 + 1];
                float b0 = bias[e*DD + col], b1v = bias[e*DD + col + 1];
                if (PHASE == 1) {
                    v0 = gelu_exact(v0 + b0);
                    v1 = gelu_exact(v1 + b1v);
                    *(__half2*)(&g_hh[gi]) = __floats2half2_rn(v0, v1);
                } else {
                    float2 xg = make_float2(0.f, 0.f);
                    if (xrow[mt][hf]) xg = *(const float2*)&xrow[mt][hf][col];
                    float o0 = v0 + b0  + xg.x;
                    float o1 = v1 + b1v + xg.y;
                    __half2 h2 = __floats2half2_rn(o0, o1);
                    *(__half2*)(&g_yh[gi]) = h2;
                    // stats from the ROUNDED values (self-consistent LN of stored y)
                    float o0r = __half2float(__low2half(h2));
                    float o1r = __half2float(__high2half(h2));
                    psum[mt][hf] += o0r + o1r;
                    psq[mt][hf]  += o0r*o0r + o1r*o1r;
                }
            }
        }
    if (PHASE == 2) {
        #pragma unroll
        for (int mt = 0; mt < 4; mt++)
            #pragma unroll
            for (int hf = 0; hf < 2; hf++) {
                #pragma unroll
                for (int o = 1; o <= 2; o <<= 1) {
                    psum[mt][hf] += __shfl_xor_sync(0xffffffffu, psum[mt][hf], o);
                    psq[mt][hf]  += __shfl_xor_sync(0xffffffffu, psq[mt][hf], o);
                }
            }
        if ((lane & 3) == 0) {
            #pragma unroll
            for (int mt = 0; mt < 4; mt++)
                #pragma unroll
                for (int hf = 0; hf < 2; hf++) {
                    int lrow = wm*64 + mt*16 + (lane >> 2) + hf*8;
                    float2 v; v.x = psum[mt][hf]; v.y = psq[mt][hf];
                    sp[wn][lrow] = v;
                }
        }
        __syncthreads();
        if (t < 128) {
            float2 a0 = sp[0][t], a1 = sp[1][t], a2 = sp[2][t], a3 = sp[3][t];
            float2 r; r.x = ((a0.x + a1.x) + a2.x) + a3.x; r.y = ((a0.y + a1.y) + a2.y) + a3.y;
            g_part[(size_t)(row0 + t)*8 + blockIdx.y] = r;
        }
    }
}

// ------------------------ K5: LN stats from partials ------------------------
__global__ void k_stats() {
    int p = blockIdx.x * 256 + threadIdx.x;
    float s = 0.f, q = 0.f;
    #pragma unroll
    for (int i = 0; i < 8; i++) {
        float2 v = g_part[(size_t)p*8 + i];
        s += v.x; q += v.y;
    }
    float mu = s * (1.f/1024.f);
    float var = q * (1.f/1024.f) - mu*mu;
    g_mu[p] = mu;
    g_rs[p] = rsqrtf(fmaxf(var, 0.f) + 1e-5f);
}

// ------------------------ K6: deterministic segment reduction (4-way split, fp16 y) ------------------------
__global__ void __launch_bounds__(512) k_reduce(const float* __restrict__ lng,
                                                const float* __restrict__ lnb) {
    __shared__ float sp2[4][128];
    int k = blockIdx.x;
    int t = threadIdx.x;
    int dl = t & 127, chunk = t >> 7;
    int d = blockIdx.y * 128 + dl;
    int e = k >> 3, b = k & 7;
    int st = g_keystart[k], c = g_cnt[k];
    int i0 = (c * chunk) >> 2, i1 = (c * (chunk + 1)) >> 2;
    float s = 0.f;
    #pragma unroll 4
    for (int i = i0; i < i1; i++) {
        int p = st + i;
        s += (__half2float(g_yh[(size_t)p*DD + d]) - g_mu[p]) * g_rs[p];
    }
    sp2[chunk][dl] = s;
    __syncthreads();
    if (chunk == 0) {
        float tot = ((sp2[0][dl] + sp2[1][dl]) + sp2[2][dl]) + sp2[3][dl];
        g_pre[(b*8 + e)*DD + d] = lng[e*DD + d] * tot + (float)c * lnb[e*DD + d];
    }
}

// ------------------------ K7: final LN ------------------------
__global__ void k_final(const float* __restrict__ gng, const float* __restrict__ gnb,
                        float* __restrict__ out) {
    __shared__ float red[8];
    int row = blockIdx.x, t = threadIdx.x;  // 256 threads
    float v[4];
    #pragma unroll
    for (int i = 0; i < 4; i++) v[i] = g_pre[row*DD + t + i*256];
    float s = 0.f;
    #pragma unroll
    for (int i = 0; i < 4; i++) s += v[i];
    s = bsum(s, red, 8);
    float mu = s * (1.f/1024.f);
    float q = 0.f;
    #pragma unroll
    for (int i = 0; i < 4; i++) { float d = v[i] - mu; q += d*d; }
    q = bsum(q, red, 8);
    float rs = rsqrtf(q*(1.f/1024.f) + 1e-5f);
    #pragma unroll
    for (int i = 0; i < 4; i++) {
        int d = t + i*256;
        out[row*DD + d] = (v[i] - mu) * rs * gng[d] + gnb[d];
    }
}

// ------------------------ launch ------------------------
extern "C" void kernel_launch(void* const* d_in, const int* in_sizes, int n_in,
                              void* d_out, int out_size) {
    const float* x     = (const float*)d_in[0];
    const float* Wg    = (const float*)d_in[2];
    const float* bg    = (const float*)d_in[3];
    const float* W1    = (const float*)d_in[4];
    const float* b1    = (const float*)d_in[5];
    const float* W2    = (const float*)d_in[6];
    const float* b2    = (const float*)d_in[7];
    const float* lng   = (const float*)d_in[8];
    const float* lnb   = (const float*)d_in[9];
    const float* gng   = (const float*)d_in[10];
    const float* gnb   = (const float*)d_in[11];
    float* out = (float*)d_out;

    cudaFuncSetAttribute(k_gemm<1>, cudaFuncAttributeMaxDynamicSharedMemorySize, GEMM_SMEM);
    cudaFuncSetAttribute(k_gemm<2>, cudaFuncAttributeMaxDynamicSharedMemorySize, GEMM_SMEM);

    k_gatehist<<<NBLK, 512>>>(x, Wg, bg);                         // 0
    k_scanscatter<<<NBLK, 128>>>();                               // 1
    k_gatherconvert<<<RPAD, 256>>>(x, W1, W2);                    // 2
    k_gemm<1><<<dim3(RPAD/128, 8), 256, GEMM_SMEM>>>(b1, x);      // 3  <- profiled launch
    k_gemm<2><<<dim3(RPAD/128, 8), 256, GEMM_SMEM>>>(b2, x);      // 4
    k_stats<<<RPAD/256, 256>>>();                                 // 5
    k_reduce<<<dim3(NKEY, 8), 512>>>(lng, lnb);                   // 6
    k_final<<<NKEY, 256>>>(gng, gnb, out);                        // 7
}